// round 8
// baseline (speedup 1.0000x reference)
#include <cuda_runtime.h>
#include <cuda_fp16.h>
#include <math.h>
#include <stdint.h>

#define Nn 4096
#define Hh 4
#define NWORDS 128   // Nn/32

// ---------------- scratch (static device globals; no allocation) -------------
__device__ uint32_t g_mask[Nn * NWORDS];          // 2 MB packed adjacency
__device__ float g_Wh[Hh * Nn * 64];              // fp32 Wh (for fe_kernel)
__device__ __half g_Wh16[Hh * Nn * 64];           // fp16 Wh (for agg cp.async)
__device__ float2 g_E1[Hh * Nn];                  // (e^f1, e^{0.2 f1}) per node
__device__ float2 g_E2[Hh * Nn];                  // (e^f2, e^{0.2 f2}) per node
__device__ float g_h1[Nn * 256];
__device__ float g_h2[Nn * 128];
__device__ float g_h3[Nn * 64];

static __device__ __forceinline__ uint32_t smem_cast(const void* p) {
    return (uint32_t)__cvta_generic_to_shared(p);
}

static __device__ __forceinline__ void ldsm_x4(uint32_t* r, uint32_t addr) {
    asm volatile("ldmatrix.sync.aligned.m8n8.x4.shared.b16 {%0,%1,%2,%3}, [%4];"
                 : "=r"(r[0]), "=r"(r[1]), "=r"(r[2]), "=r"(r[3]) : "r"(addr));
}

static __device__ __forceinline__ void ldsm_x4t(uint32_t* r, uint32_t addr) {
    asm volatile("ldmatrix.sync.aligned.m8n8.x4.trans.shared.b16 {%0,%1,%2,%3}, [%4];"
                 : "=r"(r[0]), "=r"(r[1]), "=r"(r[2]), "=r"(r[3]) : "r"(addr));
}

template <int BYTES>
static __device__ __forceinline__ void cp_async(uint32_t dst, const void* src) {
    asm volatile("cp.async.ca.shared.global [%0], [%1], %2;"
                 :: "r"(dst), "l"(src), "n"(BYTES));
}
static __device__ __forceinline__ void cp_commit() {
    asm volatile("cp.async.commit_group;");
}
static __device__ __forceinline__ void cp_wait0() {
    asm volatile("cp.async.wait_group 0;");
}

// ---------------- pack adjacency into bitmask --------------------------------
__global__ void pack_mask_kernel(const int* __restrict__ adj) {
    int idx = blockIdx.x * blockDim.x + threadIdx.x;  // one thread per 32-bit word
    int i = idx >> 7;
    int w = idx & 127;
    const int4* p = reinterpret_cast<const int4*>(adj + (size_t)i * Nn + (w << 5));
    uint32_t m = 0u;
#pragma unroll
    for (int q = 0; q < 8; q++) {
        int4 v = p[q];
        if (v.x) m |= 1u << (q * 4 + 0);
        if (v.y) m |= 1u << (q * 4 + 1);
        if (v.z) m |= 1u << (q * 4 + 2);
        if (v.w) m |= 1u << (q * 4 + 3);
    }
    g_mask[idx] = m;
}

// ---------------- Wh = x @ W[h]  (per head); writes fp32 + fp16 --------------
template <int FIN, int O, int TM, int TN>
__global__ __launch_bounds__(256) void gemm_wh_kernel(const float* __restrict__ x,
                                                      const float* __restrict__ W) {
    const int h = blockIdx.y;
    const int n0 = blockIdx.x * 128;
    const int t = threadIdx.x;
    __shared__ float xs[32][132];  // [f][row], padded, 16B-aligned rows
    __shared__ float ws[32][O];    // [f][o]
    const int CG = O / TN;
    const int rg = t / CG, cg = t % CG;
    float acc[TM][TN];
#pragma unroll
    for (int k = 0; k < TM; k++)
#pragma unroll
        for (int u = 0; u < TN; u++) acc[k][u] = 0.f;
    const float* Wc = W + (size_t)h * FIN * O;
    for (int f0 = 0; f0 < FIN; f0 += 32) {
        __syncthreads();
#pragma unroll
        for (int k = 0; k < 16; k++) {
            int idx = t + k * 256;
            int f = idx & 31, row = idx >> 5;
            xs[f][row] = x[(size_t)(n0 + row) * FIN + f0 + f];
        }
#pragma unroll
        for (int k = 0; k < (32 * O) / 256; k++) {
            int idx = t + k * 256;
            int o = idx % O, f = idx / O;
            ws[f][o] = Wc[(size_t)(f0 + f) * O + o];
        }
        __syncthreads();
#pragma unroll 8
        for (int f = 0; f < 32; f++) {
            float xv[TM], wv[TN];
#pragma unroll
            for (int q = 0; q < TM / 4; q++)
                *(float4*)&xv[q * 4] = *(const float4*)&xs[f][rg * TM + q * 4];
            if (TN >= 4) {
#pragma unroll
                for (int q = 0; q < TN / 4; q++)
                    *(float4*)&wv[q * 4] = *(const float4*)&ws[f][cg * TN + q * 4];
            } else {
                *(float2*)&wv[0] = *(const float2*)&ws[f][cg * TN];
            }
#pragma unroll
            for (int k = 0; k < TM; k++)
#pragma unroll
                for (int u = 0; u < TN; u++) acc[k][u] += xv[k] * wv[u];
        }
    }
#pragma unroll
    for (int k = 0; k < TM; k++) {
        int n = n0 + rg * TM + k;
#pragma unroll
        for (int u = 0; u < TN; u++) {
            size_t idx = ((size_t)h * Nn + n) * O + cg * TN + u;
            g_Wh[idx] = acc[k][u];
            g_Wh16[idx] = __float2half(acc[k][u]);
        }
    }
}

// ---------------- per-node attention scalars ---------------------------------
template <int O>
__global__ void fe_kernel(const float* __restrict__ a) {
    int idx = blockIdx.x * 256 + threadIdx.x;  // over Hh*Nn
    int h = idx >> 12;                          // / Nn
    const float* wr = g_Wh + (size_t)idx * O;
    const float* av = a + h * 2 * O;
    float f1 = 0.f, f2 = 0.f;
#pragma unroll
    for (int o = 0; o < O; o++) {
        float w = wr[o];
        f1 += w * av[o];
        f2 += w * av[O + o];
    }
    g_E1[idx] = make_float2(expf(f1), expf(0.2f * f1));
    g_E2[idx] = make_float2(expf(f2), expf(0.2f * f2));
}

// ---------------- fp16 tensor-core masked-softmax aggregation ----------------
// w_ij = exp(leaky(f1_i+f2_j)) = max(e^f1*e^f2, e^{0.2f1}*e^{0.2f2}), fp16.
// 64-row CTA tile, THREADS threads (16 warps for O>=32), double-buffered smem,
// ONE barrier per chunk. Weights piped through registers; Wh tile streamed via
// cp.async from pre-converted g_Wh16. Fragments via ldmatrix (x4 / x4.trans).
template <int O, int THREADS>
__global__ __launch_bounds__(THREADS) void agg_mma_kernel(float* __restrict__ out,
                                                          int HO) {
    constexpr int NWARPS = THREADS / 32;
    constexpr int NW_M = 4;                     // warp grid rows (WM=16)
    constexpr int NW_N = NWARPS / NW_M;         // warp grid cols
    constexpr int WN = O / NW_N;                // cols per warp
    constexpr int NT = WN / 8;                  // n8 tiles per warp
    constexpr int SWS = 40;                     // sW stride (halves), 80B rows
    constexpr int SBS = O + 8;                  // sWh stride (halves)
    constexpr int TPR = THREADS / 64;           // weight producers per row
    constexpr int KPT = 32 / TPR;               // k's per producer thread
    constexpr int CPB = 64 * O / THREADS;       // cp.async bytes per thread

    __shared__ __align__(16) __half sW[2][64][SWS];   // weights [row][k]
    __shared__ __align__(16) __half sWh[2][32][SBS];  // Wh chunk [k][o]
    __shared__ float sZq[THREADS];
    __shared__ float sZ[64];

    const int h = blockIdx.y;
    const int n0 = blockIdx.x * 64;
    const int t = threadIdx.x;
    const int lane = t & 31, wid = t >> 5;
    const int row0 = (wid / NW_N) * 16, col0 = (wid % NW_N) * WN;

    // weight-producer mapping: TPR threads per row, contiguous KPT-k segments
    const int rq = t / TPR, kq = t % TPR;
    const float2 e1 = g_E1[h * Nn + n0 + rq];
    const float2* E2H = g_E2 + h * Nn;
    const uint32_t* mrow = g_mask + (size_t)(n0 + rq) * NWORDS;

    // cp.async mapping: thread copies CPB contiguous bytes of the 32xO tile
    const int ci = t * CPB;
    const int cjj = ci / (2 * O), coh = (ci % (2 * O)) / 2;
    const __half* whsrc = g_Wh16 + ((size_t)h * Nn + cjj) * O + coh;

    float acc[NT][4];
#pragma unroll
    for (int nt = 0; nt < NT; nt++)
#pragma unroll
        for (int q = 0; q < 4; q++) acc[nt][q] = 0.f;
    float zloc = 0.f;

    uint32_t wreg[KPT / 2];

    auto produce_w = [&](int c) {
        const int j0 = c << 5;
        uint32_t m = mrow[c] >> (kq * KPT);
#pragma unroll
        for (int b = 0; b < KPT; b += 2) {
            float2 e2a = E2H[j0 + kq * KPT + b];
            float2 e2b = E2H[j0 + kq * KPT + b + 1];
            float wa = ((m >> b) & 1u) ? fmaxf(e1.x * e2a.x, e1.y * e2a.y) : 0.f;
            float wb = ((m >> (b + 1)) & 1u) ? fmaxf(e1.x * e2b.x, e1.y * e2b.y) : 0.f;
            __half2 hw = __floats2half2_rn(wa, wb);
            wreg[b >> 1] = *(uint32_t*)&hw;
        }
    };
    auto issue_wh = [&](int c, int buf) {
        cp_async<CPB>(smem_cast(&sWh[buf][cjj][coh]), whsrc + (size_t)(c << 5) * O);
        cp_commit();
    };

    produce_w(0);
    issue_wh(0, 0);

    for (int c = 0; c < NWORDS; c++) {
        const int buf = c & 1;
        // store weights(c), accumulate Z from fp16-rounded values
#pragma unroll
        for (int i = 0; i < KPT / 2; i++) {
            *(uint32_t*)&sW[buf][rq][kq * KPT + i * 2] = wreg[i];
            float2 f = __half22float2(*(__half2*)&wreg[i]);
            zloc += f.x + f.y;
        }
        cp_wait0();       // this thread's Wh(buf) copy landed
        __syncthreads();  // everyone's stores + copies visible
        if (c + 1 < NWORDS) {
            produce_w(c + 1);
            issue_wh(c + 1, buf ^ 1);
        }
        // consume chunk c from smem[buf]
        uint32_t a[2][4], bfr[NT][4];
#pragma unroll
        for (int ks = 0; ks < 2; ks++)
            ldsm_x4(a[ks], smem_cast(&sW[buf][row0 + (lane & 15)]
                                        [ks * 16 + ((lane >> 4) & 1) * 8]));
#pragma unroll
        for (int nt = 0; nt < NT; nt++)
            ldsm_x4t(bfr[nt], smem_cast(&sWh[buf][lane][col0 + nt * 8]));
#pragma unroll
        for (int ks = 0; ks < 2; ks++)
#pragma unroll
            for (int nt = 0; nt < NT; nt++)
                asm volatile(
                    "mma.sync.aligned.m16n8k16.row.col.f32.f16.f16.f32 "
                    "{%0,%1,%2,%3}, {%4,%5,%6,%7}, {%8,%9}, {%0,%1,%2,%3};"
                    : "+f"(acc[nt][0]), "+f"(acc[nt][1]),
                      "+f"(acc[nt][2]), "+f"(acc[nt][3])
                    : "r"(a[ks][0]), "r"(a[ks][1]), "r"(a[ks][2]), "r"(a[ks][3]),
                      "r"(bfr[nt][2 * ks]), "r"(bfr[nt][2 * ks + 1]));
    }
    // reduce Z per row (TPR producer threads per row)
    sZq[t] = zloc;
    __syncthreads();
    if (t < 64) {
        float z = 0.f;
#pragma unroll
        for (int i = 0; i < TPR; i++) z += sZq[t * TPR + i];
        sZ[t] = z;
    }
    __syncthreads();
    // epilogue: normalize, ELU, head-concat store
    {
        int r = row0 + (lane >> 2);
        float iz0 = 1.f / sZ[r];
        float iz1 = 1.f / sZ[r + 8];
#pragma unroll
        for (int nt = 0; nt < NT; nt++) {
            int cb = col0 + nt * 8 + (lane & 3) * 2;
            float v0 = acc[nt][0] * iz0;
            float v1 = acc[nt][1] * iz0;
            float v2 = acc[nt][2] * iz1;
            float v3 = acc[nt][3] * iz1;
            v0 = v0 > 0.f ? v0 : expm1f(v0);
            v1 = v1 > 0.f ? v1 : expm1f(v1);
            v2 = v2 > 0.f ? v2 : expm1f(v2);
            v3 = v3 > 0.f ? v3 : expm1f(v3);
            *(float2*)&out[(size_t)(n0 + r) * HO + h * O + cb] = make_float2(v0, v1);
            *(float2*)&out[(size_t)(n0 + r + 8) * HO + h * O + cb] = make_float2(v2, v3);
        }
    }
}

// ---------------- final linear + log_softmax ---------------------------------
__global__ void final_kernel(const float* __restrict__ Wlin,
                             const float* __restrict__ blin,
                             float* __restrict__ out) {
    int lane = threadIdx.x & 31;
    int n = (blockIdx.x * blockDim.x + threadIdx.x) >> 5;  // one warp per row
    const float* hr = g_h3 + (size_t)n * 64;
    float v1 = -INFINITY;
    float a0 = blin[lane];
    float a1v = (lane < 8) ? blin[lane + 32] : 0.f;
#pragma unroll 16
    for (int k = 0; k < 64; k++) {
        float hv = hr[k];
        a0 += hv * Wlin[k * 40 + lane];
        if (lane < 8) a1v += hv * Wlin[k * 40 + lane + 32];
    }
    float v0 = a0;
    if (lane < 8) v1 = a1v;
    float m = fmaxf(v0, v1);
#pragma unroll
    for (int off = 16; off; off >>= 1) m = fmaxf(m, __shfl_xor_sync(0xffffffffu, m, off));
    float e = expf(v0 - m) + ((lane < 8) ? expf(v1 - m) : 0.f);
#pragma unroll
    for (int off = 16; off; off >>= 1) e += __shfl_xor_sync(0xffffffffu, e, off);
    float lse = m + logf(e);
    out[(size_t)n * 40 + lane] = v0 - lse;
    if (lane < 8) out[(size_t)n * 40 + lane + 32] = v1 - lse;
}

// ---------------- launch -----------------------------------------------------
extern "C" void kernel_launch(void* const* d_in, const int* in_sizes, int n_in,
                              void* d_out, int out_size) {
    const float* x    = (const float*)d_in[0];
    const int*   adj  = (const int*)d_in[1];
    const float* W1   = (const float*)d_in[2];
    const float* a1   = (const float*)d_in[3];
    const float* W2   = (const float*)d_in[4];
    const float* a2   = (const float*)d_in[5];
    const float* W3   = (const float*)d_in[6];
    const float* a3   = (const float*)d_in[7];
    const float* Wlin = (const float*)d_in[8];
    const float* blin = (const float*)d_in[9];
    float* out = (float*)d_out;

    float *h1, *h2, *h3;
    cudaGetSymbolAddress((void**)&h1, g_h1);
    cudaGetSymbolAddress((void**)&h2, g_h2);
    cudaGetSymbolAddress((void**)&h3, g_h3);

    pack_mask_kernel<<<(Nn * NWORDS) / 256, 256>>>(adj);

    dim3 ggrid(Nn / 128, Hh);
    dim3 agrid(Nn / 64, Hh);

    // stage 1: Fin=512, O=64
    gemm_wh_kernel<512, 64, 8, 4><<<ggrid, 256>>>(x, W1);
    fe_kernel<64><<<(Hh * Nn) / 256, 256>>>(a1);
    agg_mma_kernel<64, 512><<<agrid, 512>>>(h1, 256);

    // stage 2: Fin=256, O=32
    gemm_wh_kernel<256, 32, 4, 4><<<ggrid, 256>>>(h1, W2);
    fe_kernel<32><<<(Hh * Nn) / 256, 256>>>(a2);
    agg_mma_kernel<32, 512><<<agrid, 512>>>(h2, 128);

    // stage 3: Fin=128, O=16
    gemm_wh_kernel<128, 16, 4, 2><<<ggrid, 256>>>(h2, W3);
    fe_kernel<16><<<(Hh * Nn) / 256, 256>>>(a3);
    agg_mma_kernel<16, 256><<<agrid, 256>>>(h3, 64);

    final_kernel<<<(Nn * 32) / 256, 256>>>(Wlin, blin, out);
}